// round 15
// baseline (speedup 1.0000x reference)
#include <cuda_runtime.h>
#include <cstdint>

// FP8 E4M3 multiplier over "bit-vector" encoded tensors.
// Each fp8 value is 8 float32 bits [s, e3, e2, e1, e0, m2, m1, m0],
// each "bit" float exactly 0.0f (0x00000000) or 1.0f (0x3f800000).
//
// Converged family (bench 62.1 +/- 0.5 us, ~85% of HBM spec): 1 elem/thread,
// one-shot grid, sm_100+ 256-bit global accesses, branch-free integer
// decode/encode, 24 regs, default cache policy. R13 probe: 128-thr blocks.

__device__ __forceinline__ unsigned bw(int bit) {      // bit(0/1) -> 0.0f/1.0f raw
    return (unsigned)(-bit) & 0x3f800000u;
}

__device__ __forceinline__ void ldg256(const void* p,
                                       unsigned& r0, unsigned& r1, unsigned& r2, unsigned& r3,
                                       unsigned& r4, unsigned& r5, unsigned& r6, unsigned& r7)
{
    asm volatile("ld.global.v8.b32 {%0,%1,%2,%3,%4,%5,%6,%7}, [%8];"
                 : "=r"(r0), "=r"(r1), "=r"(r2), "=r"(r3),
                   "=r"(r4), "=r"(r5), "=r"(r6), "=r"(r7)
                 : "l"(p));
}

__device__ __forceinline__ void stg256(void* p,
                                       unsigned r0, unsigned r1, unsigned r2, unsigned r3,
                                       unsigned r4, unsigned r5, unsigned r6, unsigned r7)
{
    asm volatile("st.global.v8.b32 [%0], {%1,%2,%3,%4,%5,%6,%7,%8};"
                 :: "l"(p),
                    "r"(r0), "r"(r1), "r"(r2), "r"(r3),
                    "r"(r4), "r"(r5), "r"(r6), "r"(r7)
                 : "memory");
}

__global__ void __launch_bounds__(128) fp8mul_kernel(
    const unsigned* __restrict__ a8,
    const unsigned* __restrict__ b8,
    unsigned* __restrict__ o8,
    int n)
{
    int i = blockIdx.x * blockDim.x + threadIdx.x;
    if (i >= n) return;

    unsigned a0,a1,a2,a3,a4,a5,a6,a7;
    unsigned c0,c1,c2,c3,c4,c5,c6,c7;
    ldg256(a8 + 8ll * i, a0,a1,a2,a3,a4,a5,a6,a7);
    ldg256(b8 + 8ll * i, c0,c1,c2,c3,c4,c5,c6,c7);

    // decode: bit = (w >> 29) & 1
    int sa =  (a0 >> 29) & 1;
    int ea = (((a1 >> 29) & 1) << 3) | (((a2 >> 29) & 1) << 2)
           | (((a3 >> 29) & 1) << 1) |  ((a4 >> 29) & 1);
    int ma = (((a5 >> 29) & 1) << 2) | (((a6 >> 29) & 1) << 1)
           |  ((a7 >> 29) & 1);
    int sb =  (c0 >> 29) & 1;
    int eb = (((c1 >> 29) & 1) << 3) | (((c2 >> 29) & 1) << 2)
           | (((c3 >> 29) & 1) << 1) |  ((c4 >> 29) & 1);
    int mb = (((c5 >> 29) & 1) << 2) | (((c6 >> 29) & 1) << 1)
           |  ((c7 >> 29) & 1);

    int sig_a = (ea == 0) ? ma : (ma + 8);
    int sig_b = (eb == 0) ? mb : (mb + 8);
    int exa = ((ea == 0) ? 1 : ea) - 7;
    int exb = ((eb == 0) ? 1 : eb) - 7;

    int M = sig_a * sig_b;          // exact product, <= 225
    int E = exa + exb - 6;          // value = M * 2^E

    int p = (M > 0) ? (31 - __clz(M)) : 0;   // MSB position of M
    int eb_out = E + p + 7;

    // ---- normal path: RNE round to 3 mantissa bits (branch-free) ----
    int sh = p - 3;
    int shp = sh > 0 ? sh : 0;
    int q = M >> shp;
    int rem = M - (q << shp);
    int half = (1 << shp) >> 1;               // 0 when shp==0
    int up = ((rem > half) | ((rem == half) & (q & 1))) & (shp > 0);
    int mant4 = (q + up) << (sh < 0 ? -sh : 0);
    int carry = mant4 >> 4;                   // rounding overflow
    mant4 = (mant4 == 16) ? 8 : mant4;
    int e_n = eb_out + carry;
    int m_n = mant4 - 8;
    int nan = e_n >= 16;
    e_n = nan ? 15 : e_n;
    m_n = nan ? 7 : m_n;

    // ---- subnormal path (eb_out <= 0): mant = RNE(M * 2^(E+9)) ----
    int t = E + 9;
    int shs = (-t) < 0 ? 0 : ((-t) > 30 ? 30 : -t);
    int qs = M >> shs;
    int rems = M - (qs << shs);
    int halfs = (1 << shs) >> 1;
    int ups = ((rems > halfs) | ((rems == halfs) & (qs & 1))) & (shs > 0);
    int mant_s = (qs + ups) << (t > 0 ? t : 0);
    int e_s = (mant_s >= 8) ? 1 : 0;
    int m_s = (mant_s >= 8) ? 0 : mant_s;

    // ---- select ----
    bool is_sub = (eb_out <= 0);
    int e_o = is_sub ? e_s : e_n;
    int m_o = is_sub ? m_s : m_n;
    bool zero = (M == 0);
    e_o = zero ? 0 : e_o;
    m_o = zero ? 0 : m_o;
    int s_o = sa ^ sb;

    stg256(o8 + 8ll * i,
           bw(s_o),
           bw((e_o >> 3) & 1),
           bw((e_o >> 2) & 1),
           bw((e_o >> 1) & 1),
           bw(e_o & 1),
           bw((m_o >> 2) & 1),
           bw((m_o >> 1) & 1),
           bw(m_o & 1));
}

extern "C" void kernel_launch(void* const* d_in, const int* in_sizes, int n_in,
                              void* d_out, int out_size)
{
    const unsigned* a = (const unsigned*)d_in[0];
    const unsigned* b = (const unsigned*)d_in[1];
    unsigned* o = (unsigned*)d_out;
    int n = in_sizes[0] / 8;                 // fp8 element count
    int threads = 128;
    int blocks = (n + threads - 1) / threads;
    fp8mul_kernel<<<blocks, threads>>>(a, b, o, n);
}

// round 16
// speedup vs baseline: 1.0150x; 1.0150x over previous
#include <cuda_runtime.h>
#include <cstdint>

// FP8 E4M3 multiplier over "bit-vector" encoded tensors.
// Each fp8 value is 8 float32 bits [s, e3, e2, e1, e0, m2, m1, m0],
// each "bit" float exactly 0.0f (0x00000000) or 1.0f (0x3f800000).
//
// FINAL (converged, session best 61.95us / ~85% of HBM spec):
//   - 1 element/thread, one-shot 16384-CTA grid, 256-thread blocks
//   - sm_100+ 256-bit global accesses (ld/st.global.v8.b32)
//   - branch-free integer-domain decode/encode, 24 regs
//   - default cache policy
// Pure HBM-bound: 384 MiB compulsory, perfectly coalesced traffic.
// Exhaustive sweeps (block size, elems/thread, persistence, cache hints,
// decode domain, access width) all land on this memory floor.

__device__ __forceinline__ unsigned bw(int bit) {      // bit(0/1) -> 0.0f/1.0f raw
    return (unsigned)(-bit) & 0x3f800000u;
}

__device__ __forceinline__ void ldg256(const void* p,
                                       unsigned& r0, unsigned& r1, unsigned& r2, unsigned& r3,
                                       unsigned& r4, unsigned& r5, unsigned& r6, unsigned& r7)
{
    asm volatile("ld.global.v8.b32 {%0,%1,%2,%3,%4,%5,%6,%7}, [%8];"
                 : "=r"(r0), "=r"(r1), "=r"(r2), "=r"(r3),
                   "=r"(r4), "=r"(r5), "=r"(r6), "=r"(r7)
                 : "l"(p));
}

__device__ __forceinline__ void stg256(void* p,
                                       unsigned r0, unsigned r1, unsigned r2, unsigned r3,
                                       unsigned r4, unsigned r5, unsigned r6, unsigned r7)
{
    asm volatile("st.global.v8.b32 [%0], {%1,%2,%3,%4,%5,%6,%7,%8};"
                 :: "l"(p),
                    "r"(r0), "r"(r1), "r"(r2), "r"(r3),
                    "r"(r4), "r"(r5), "r"(r6), "r"(r7)
                 : "memory");
}

__global__ void __launch_bounds__(256) fp8mul_kernel(
    const unsigned* __restrict__ a8,
    const unsigned* __restrict__ b8,
    unsigned* __restrict__ o8,
    int n)
{
    int i = blockIdx.x * blockDim.x + threadIdx.x;
    if (i >= n) return;

    unsigned a0,a1,a2,a3,a4,a5,a6,a7;
    unsigned c0,c1,c2,c3,c4,c5,c6,c7;
    ldg256(a8 + 8ll * i, a0,a1,a2,a3,a4,a5,a6,a7);
    ldg256(b8 + 8ll * i, c0,c1,c2,c3,c4,c5,c6,c7);

    // decode: bit = (w >> 29) & 1
    int sa =  (a0 >> 29) & 1;
    int ea = (((a1 >> 29) & 1) << 3) | (((a2 >> 29) & 1) << 2)
           | (((a3 >> 29) & 1) << 1) |  ((a4 >> 29) & 1);
    int ma = (((a5 >> 29) & 1) << 2) | (((a6 >> 29) & 1) << 1)
           |  ((a7 >> 29) & 1);
    int sb =  (c0 >> 29) & 1;
    int eb = (((c1 >> 29) & 1) << 3) | (((c2 >> 29) & 1) << 2)
           | (((c3 >> 29) & 1) << 1) |  ((c4 >> 29) & 1);
    int mb = (((c5 >> 29) & 1) << 2) | (((c6 >> 29) & 1) << 1)
           |  ((c7 >> 29) & 1);

    int sig_a = (ea == 0) ? ma : (ma + 8);
    int sig_b = (eb == 0) ? mb : (mb + 8);
    int exa = ((ea == 0) ? 1 : ea) - 7;
    int exb = ((eb == 0) ? 1 : eb) - 7;

    int M = sig_a * sig_b;          // exact product, <= 225
    int E = exa + exb - 6;          // value = M * 2^E

    int p = (M > 0) ? (31 - __clz(M)) : 0;   // MSB position of M
    int eb_out = E + p + 7;

    // ---- normal path: RNE round to 3 mantissa bits (branch-free) ----
    int sh = p - 3;
    int shp = sh > 0 ? sh : 0;
    int q = M >> shp;
    int rem = M - (q << shp);
    int half = (1 << shp) >> 1;               // 0 when shp==0
    int up = ((rem > half) | ((rem == half) & (q & 1))) & (shp > 0);
    int mant4 = (q + up) << (sh < 0 ? -sh : 0);
    int carry = mant4 >> 4;                   // rounding overflow
    mant4 = (mant4 == 16) ? 8 : mant4;
    int e_n = eb_out + carry;
    int m_n = mant4 - 8;
    int nan = e_n >= 16;
    e_n = nan ? 15 : e_n;
    m_n = nan ? 7 : m_n;

    // ---- subnormal path (eb_out <= 0): mant = RNE(M * 2^(E+9)) ----
    int t = E + 9;
    int shs = (-t) < 0 ? 0 : ((-t) > 30 ? 30 : -t);
    int qs = M >> shs;
    int rems = M - (qs << shs);
    int halfs = (1 << shs) >> 1;
    int ups = ((rems > halfs) | ((rems == halfs) & (qs & 1))) & (shs > 0);
    int mant_s = (qs + ups) << (t > 0 ? t : 0);
    int e_s = (mant_s >= 8) ? 1 : 0;
    int m_s = (mant_s >= 8) ? 0 : mant_s;

    // ---- select ----
    bool is_sub = (eb_out <= 0);
    int e_o = is_sub ? e_s : e_n;
    int m_o = is_sub ? m_s : m_n;
    bool zero = (M == 0);
    e_o = zero ? 0 : e_o;
    m_o = zero ? 0 : m_o;
    int s_o = sa ^ sb;

    stg256(o8 + 8ll * i,
           bw(s_o),
           bw((e_o >> 3) & 1),
           bw((e_o >> 2) & 1),
           bw((e_o >> 1) & 1),
           bw(e_o & 1),
           bw((m_o >> 2) & 1),
           bw((m_o >> 1) & 1),
           bw(m_o & 1));
}

extern "C" void kernel_launch(void* const* d_in, const int* in_sizes, int n_in,
                              void* d_out, int out_size)
{
    const unsigned* a = (const unsigned*)d_in[0];
    const unsigned* b = (const unsigned*)d_in[1];
    unsigned* o = (unsigned*)d_out;
    int n = in_sizes[0] / 8;                 // fp8 element count
    int threads = 256;
    int blocks = (n + threads - 1) / threads;
    fp8mul_kernel<<<blocks, threads>>>(a, b, o, n);
}